// round 15
// baseline (speedup 1.0000x reference)
#include <cuda_runtime.h>
#include <cuda_fp16.h>

#define NN 200000
#define EE 3200000
#define CAP 64                    // per-node bucket capacity (P(overflow) ~ 1e-10)

// ---------------- static device scratch ----------------
__device__ int      g_deg[NN];          // out-degree by src (statically zero; reset by last comb)
__device__ int      g_cnt[NN];          // in-degree by dst / scatter cursor
__device__ float    g_dinv[NN];
__device__ int      g_len[NN];          // padded row length
__device__ int      g_src[NN * CAP];    // bucketed CSR
__device__ float4   g_h[NN * 8];        // raw fp32 features
__device__ float4   g_a[NN * 8];
__device__ float4   g_t[NN * 8];
__device__ float4   g_b[NN * 8];
__device__ uint2    s_h[(NN + 1) * 8];  // fp16 prescaled shadows; row NN stays zero (pad)
__device__ uint2    s_a[(NN + 1) * 8];
__device__ uint2    s_t[(NN + 1) * 8];
__device__ uint2    s_b[(NN + 1) * 8];

__device__ __forceinline__ float4* fbuf(int id) {
    switch (id) { case 0: return g_h; case 1: return g_a; case 2: return g_t; default: return g_b; }
}
__device__ __forceinline__ uint2* hbuf(int id) {
    switch (id) { case 0: return s_h; case 1: return s_a; case 2: return s_t; default: return s_b; }
}

// per-block dtype detection: 1 if edge buffer is int64
__device__ __forceinline__ int detect64(const void* ei) {
    const int* w = (const int*)ei;
    int bad = 0;
#pragma unroll
    for (int k = 0; k < 2; k++) {
        int idx = (threadIdx.x & 31) + 32 * k;
        if (w[2 * idx + 1] != 0) bad = 1;
    }
    return __all_sync(0xffffffffu, bad == 0) ? 1 : 0;
}

__device__ __forceinline__ int edge_at(const void* ei, int idx, int is64) {
    if (is64) return (int)((const long long*)ei)[idx];
    return ((const int*)ei)[idx];
}

// ---------------- single-pass scatter (counts + bucket CSR) ----------------
__global__ void k_scat(const void* ei, int e) {
    int is64 = detect64(ei);
    int i = blockIdx.x * blockDim.x + threadIdx.x;
    if (i < e) {
        int s = edge_at(ei, i, is64);
        int d = edge_at(ei, e + i, is64);
        atomicAdd(&g_deg[s], 1);
        int p = atomicAdd(&g_cnt[d], 1);
        if (p < CAP) g_src[d * CAP + p] = s;
    }
}

// ---------------- dinv + row pad + input MLP + fp16 shadow (32 thr/node) ----------------
__global__ void k_mlp(const float* __restrict__ x, const float* __restrict__ W0,
                      const float* __restrict__ b0, int n) {
    __shared__ float sw[96];
    __shared__ float sb[32];
    int tid = threadIdx.x;
    if (tid < 96) sw[tid] = W0[tid];
    if (tid < 32) sb[tid] = b0[tid];
    __syncthreads();
    int i = blockIdx.x * blockDim.x + tid;
    if (i >= n * 32) return;
    int node = i >> 5, f = i & 31;
    int dg = g_deg[node];
    float di = (dg > 0) ? rsqrtf((float)dg) : 0.f;
    int cnt = g_cnt[node];
    if (cnt > CAP) cnt = CAP;
    int pv = (cnt + 3) & ~3;
    if (pv > CAP) pv = CAP;
    if (f == 0) {
        g_dinv[node] = di;
        g_len[node] = pv;
    }
    if (f < pv - cnt) g_src[node * CAP + cnt + f] = n;   // pad -> zero shadow row
    float x0 = x[node * 3 + 0];
    float x1 = x[node * 3 + 1];
    float x2 = x[node * 3 + 2];
    float o = sb[f] + x0 * sw[f] + x1 * sw[32 + f] + x2 * sw[64 + f];
    o = fmaxf(o, 0.f);
    ((float*)g_h)[i] = o;
    float o_hi = __shfl_down_sync(0xffffffffu, o, 1);
    if ((f & 1) == 0)
        ((__half2*)s_h)[node * 16 + (f >> 1)] = __floats2half2_rn(di * o, di * o_hi);
}

// -------- fp16 quad reduce: sum 4 edge rows in fp16 (HADD2 tree), convert once, fp32 acc --------
__device__ __forceinline__ void quad4(uint2 r0, uint2 r1, uint2 r2, uint2 r3, float4& acc) {
    __half2 a0 = __hadd2(*reinterpret_cast<__half2*>(&r0.x), *reinterpret_cast<__half2*>(&r1.x));
    __half2 a1 = __hadd2(*reinterpret_cast<__half2*>(&r0.y), *reinterpret_cast<__half2*>(&r1.y));
    __half2 b0 = __hadd2(*reinterpret_cast<__half2*>(&r2.x), *reinterpret_cast<__half2*>(&r3.x));
    __half2 b1 = __hadd2(*reinterpret_cast<__half2*>(&r2.y), *reinterpret_cast<__half2*>(&r3.y));
    float2 f0 = __half22float2(__hadd2(a0, b0));
    float2 f1 = __half22float2(__hadd2(a1, b1));
    acc.x += f0.x; acc.y += f0.y; acc.z += f1.x; acc.w += f1.y;
}

// -------- fp16 group gather (bucketed, padded, 8-edge unrolled): 8-lane group per row --------
__device__ __forceinline__ float4 gatherH8(const uint2* __restrict__ rows,
                                           int s, int e, int c) {
    float4 acc = make_float4(0.f, 0.f, 0.f, 0.f);
    int i = s;
    for (; i + 8 <= e; i += 8) {
        int4 ia = __ldg((const int4*)&g_src[i]);
        int4 ib = __ldg((const int4*)&g_src[i + 4]);
        uint2 r0 = __ldg(&rows[ia.x * 8 + c]);
        uint2 r1 = __ldg(&rows[ia.y * 8 + c]);
        uint2 r2 = __ldg(&rows[ia.z * 8 + c]);
        uint2 r3 = __ldg(&rows[ia.w * 8 + c]);
        uint2 r4 = __ldg(&rows[ib.x * 8 + c]);
        uint2 r5 = __ldg(&rows[ib.y * 8 + c]);
        uint2 r6 = __ldg(&rows[ib.z * 8 + c]);
        uint2 r7 = __ldg(&rows[ib.w * 8 + c]);
        quad4(r0, r1, r2, r3, acc);
        quad4(r4, r5, r6, r7, acc);
    }
    if (i < e) {   // exactly 4 remain (rows padded to multiples of 4)
        int4 ia = __ldg((const int4*)&g_src[i]);
        uint2 r0 = __ldg(&rows[ia.x * 8 + c]);
        uint2 r1 = __ldg(&rows[ia.y * 8 + c]);
        uint2 r2 = __ldg(&rows[ia.z * 8 + c]);
        uint2 r3 = __ldg(&rows[ia.w * 8 + c]);
        quad4(r0, r1, r2, r3, acc);
    }
    return acc;
}

__device__ __forceinline__ uint2 pack4(float a, float b, float c, float d) {
    __half2 h0 = __floats2half2_rn(a, b);
    __half2 h1 = __floats2half2_rn(c, d);
    uint2 r;
    r.x = *reinterpret_cast<unsigned*>(&h0);
    r.y = *reinterpret_cast<unsigned*>(&h1);
    return r;
}

// ---------------- prop: T1 = L~ x ; warp = 4 rows, 8-lane group per row ----------------
__global__ void k_prop(int in_id, int n) {
    const uint2* __restrict__ xin = hbuf(in_id);
    int t = blockIdx.x * blockDim.x + threadIdx.x;
    int lane = threadIdx.x & 31;
    int row = ((t >> 5) << 2) + (lane >> 3);
    int c = lane & 7;
    if (row >= n) return;
    int s = row * CAP;
    int e = s + g_len[row];
    float4 acc = gatherH8(xin, s, e, c);
    float di = g_dinv[row];
    float4 r = make_float4(-di * acc.x, -di * acc.y, -di * acc.z, -di * acc.w);
    g_t[row * 8 + c] = r;
    s_t[row * 8 + c] = pack4(di * r.x, di * r.y, di * r.z, di * r.w);
}

// ---------------- fused second prop + tiled Chebyshev combine ----------------
// dense phase: 4 warps x 8 accumulators (halves sT re-read traffic vs 8 warps x 4)
__global__ void __launch_bounds__(256) k_comb(int t0_id, int resid_id, int out_id,
                       const float* __restrict__ Wc, const float* __restrict__ bc, int n,
                       int fuse_final, const float* __restrict__ W1,
                       const float* __restrict__ b1, float* __restrict__ fout) {
    __shared__ float sT[32][100];
    __shared__ float sWt[32][100];
    __shared__ float sO[32][33];
    const float4* __restrict__ t0f = fbuf(t0_id);
    float4* __restrict__ outf = fbuf(out_id);
    uint2* __restrict__ outs = hbuf(out_id);

    int tid = threadIdx.x;
    int wid = tid >> 5, lane = tid & 31;
    int base = blockIdx.x << 5;

#pragma unroll
    for (int rep = 0; rep < 12; rep++) {
        int idx = rep * 256 + tid;
        sWt[idx & 31][idx >> 5] = Wc[idx];
    }

    // gather phase: warp's 4 groups = 4 nodes
    {
        int grp = lane >> 3, c = lane & 7;
        int nl = (wid << 2) + grp;
        int node = base + nl;
        if (node < n) {
            int s = node * CAP;
            int e = s + g_len[node];
            float4 acc = gatherH8(s_t, s, e, c);
            float di = g_dinv[node];
            float4 t0 = t0f[node * 8 + c];
            float4 t1 = g_t[node * 8 + c];
            float m = -2.f * di;
            float4 t2;
            t2.x = fmaf(m, acc.x, -t0.x);
            t2.y = fmaf(m, acc.y, -t0.y);
            t2.z = fmaf(m, acc.z, -t0.z);
            t2.w = fmaf(m, acc.w, -t0.w);
            *(float4*)&sT[nl][c * 4]      = t0;
            *(float4*)&sT[nl][32 + c * 4] = t1;
            *(float4*)&sT[nl][64 + c * 4] = t2;
        }
    }
    __syncthreads();

    // dense phase: warps 0-3; warp wid -> features {wid, wid+4, ..., wid+28}, node = lane
    if (wid < 4) {
        float acc[8];
#pragma unroll
        for (int j = 0; j < 8; j++) acc[j] = __ldg(&bc[wid + 4 * j]);
#pragma unroll
        for (int kc = 0; kc < 24; kc++) {
            float4 t = *(const float4*)&sT[lane][kc * 4];
#pragma unroll
            for (int j = 0; j < 8; j++) {
                float4 w = *(const float4*)&sWt[wid + 4 * j][kc * 4];
                acc[j] += t.x * w.x + t.y * w.y + t.z * w.z + t.w * w.w;
            }
        }
#pragma unroll
        for (int j = 0; j < 8; j++) sO[lane][wid + 4 * j] = acc[j];
    }
    __syncthreads();

    // epilogue: resid + relu + stores (+ fused output layer, + counter reset on last conv)
    {
        int nl = tid >> 3, cc = tid & 7;
        int node = base + nl;
        if (node < n) {
            float4 o;
            o.x = sO[nl][cc * 4 + 0];
            o.y = sO[nl][cc * 4 + 1];
            o.z = sO[nl][cc * 4 + 2];
            o.w = sO[nl][cc * 4 + 3];
            if (resid_id >= 0) {
                float4 rv = fbuf(resid_id)[node * 8 + cc];
                o.x += rv.x; o.y += rv.y; o.z += rv.z; o.w += rv.w;
            }
            o.x = fmaxf(o.x, 0.f); o.y = fmaxf(o.y, 0.f);
            o.z = fmaxf(o.z, 0.f); o.w = fmaxf(o.w, 0.f);
            outf[node * 8 + cc] = o;
            float di = g_dinv[node];
            outs[node * 8 + cc] = pack4(di * o.x, di * o.y, di * o.z, di * o.w);
            if (fuse_final) {
                float4 wv = __ldg(&((const float4*)W1)[cc]);
                float part = o.x * wv.x + o.y * wv.y + o.z * wv.z + o.w * wv.w;
#pragma unroll
                for (int m = 1; m <= 4; m <<= 1)
                    part += __shfl_xor_sync(0xffffffffu, part, m);
                if (cc == 0) {
                    fout[node] = part + b1[0];
                    g_cnt[node] = 0;     // reset for next graph replay
                    g_deg[node] = 0;
                }
            }
        }
    }
}

// ---------------- launch ----------------
extern "C" void kernel_launch(void* const* d_in, const int* in_sizes, int n_in,
                              void* d_out, int out_size) {
    const float* x    = (const float*)d_in[0];
    const void*  ei   = d_in[1];
    const float* W0   = (const float*)d_in[2];
    const float* b0   = (const float*)d_in[3];
    const float* c11W = (const float*)d_in[4];
    const float* c11b = (const float*)d_in[5];
    const float* c12W = (const float*)d_in[6];
    const float* c12b = (const float*)d_in[7];
    const float* c21W = (const float*)d_in[8];
    const float* c21b = (const float*)d_in[9];
    const float* c22W = (const float*)d_in[10];
    const float* c22b = (const float*)d_in[11];
    const float* W1   = (const float*)d_in[12];
    const float* b1   = (const float*)d_in[13];
    float* out = (float*)d_out;

    int n = in_sizes[0] / 3;
    int e = in_sizes[1] / 2;
    if (n > NN) n = NN;
    if (e > EE) e = EE;

    const int B = 256;
    int gE  = (e + B - 1) / B;
    int gNF = (n * 32 + B - 1) / B;   // 32 thr/node (mlp)
    int gP  = (n * 8 + B - 1) / B;    // 8 thr/row (prop)
    int gT  = (n + 31) / 32;          // 32-node tiles (comb)

    // setup: 2 launches -> first k_comb is launch #4 (ncu capture target)
    k_scat<<<gE, B>>>(ei, e);
    k_mlp<<<gNF, B>>>(x, W0, b0, n);

    // ids: 0=h, 1=a, 2=t, 3=b
    // conv11: h -> a
    k_prop<<<gP, B>>>(0, n);
    k_comb<<<gT, B>>>(0, -1, 1, c11W, c11b, n, 0, W1, b1, out);
    // conv12: a -> b, resid h
    k_prop<<<gP, B>>>(1, n);
    k_comb<<<gT, B>>>(1, 0, 3, c12W, c12b, n, 0, W1, b1, out);
    // conv21: b -> a
    k_prop<<<gP, B>>>(3, n);
    k_comb<<<gT, B>>>(3, -1, 1, c21W, c21b, n, 0, W1, b1, out);
    // conv22: a -> h, resid b (+ fused output layer + counter reset)
    k_prop<<<gP, B>>>(1, n);
    k_comb<<<gT, B>>>(1, 3, 0, c22W, c22b, n, 1, W1, b1, out);
}

// round 16
// speedup vs baseline: 1.0931x; 1.0931x over previous
#include <cuda_runtime.h>
#include <cuda_fp16.h>

#define NN 200000
#define EE 3200000
#define CAP 64                    // per-node bucket capacity (P(overflow) ~ 1e-10)

// ---------------- static device scratch ----------------
__device__ int      g_deg[NN];          // out-degree by src (statically zero; reset by last comb)
__device__ int      g_cnt[NN];          // in-degree by dst / scatter cursor
__device__ float    g_dinv[NN];
__device__ int      g_len[NN];          // padded row length
__device__ int      g_src[NN * CAP];    // bucketed CSR
__device__ float4   g_h[NN * 8];        // raw fp32 features
__device__ float4   g_a[NN * 8];
__device__ float4   g_t[NN * 8];
__device__ float4   g_b[NN * 8];
__device__ uint2    s_h[(NN + 1) * 8];  // fp16 prescaled shadows; row NN stays zero (pad)
__device__ uint2    s_a[(NN + 1) * 8];
__device__ uint2    s_t[(NN + 1) * 8];
__device__ uint2    s_b[(NN + 1) * 8];

__device__ __forceinline__ float4* fbuf(int id) {
    switch (id) { case 0: return g_h; case 1: return g_a; case 2: return g_t; default: return g_b; }
}
__device__ __forceinline__ uint2* hbuf(int id) {
    switch (id) { case 0: return s_h; case 1: return s_a; case 2: return s_t; default: return s_b; }
}

// per-block dtype detection: 1 if edge buffer is int64
__device__ __forceinline__ int detect64(const void* ei) {
    const int* w = (const int*)ei;
    int bad = 0;
#pragma unroll
    for (int k = 0; k < 2; k++) {
        int idx = (threadIdx.x & 31) + 32 * k;
        if (w[2 * idx + 1] != 0) bad = 1;
    }
    return __all_sync(0xffffffffu, bad == 0) ? 1 : 0;
}

__device__ __forceinline__ int edge_at(const void* ei, int idx, int is64) {
    if (is64) return (int)((const long long*)ei)[idx];
    return ((const int*)ei)[idx];
}

// ---------------- single-pass scatter (counts + bucket CSR) ----------------
__global__ void k_scat(const void* ei, int e) {
    int is64 = detect64(ei);
    int i = blockIdx.x * blockDim.x + threadIdx.x;
    if (i < e) {
        int s = edge_at(ei, i, is64);
        int d = edge_at(ei, e + i, is64);
        atomicAdd(&g_deg[s], 1);
        int p = atomicAdd(&g_cnt[d], 1);
        if (p < CAP) g_src[d * CAP + p] = s;
    }
}

// ---------------- dinv + row pad + input MLP + fp16 shadow (32 thr/node) ----------------
__global__ void k_mlp(const float* __restrict__ x, const float* __restrict__ W0,
                      const float* __restrict__ b0, int n) {
    __shared__ float sw[96];
    __shared__ float sb[32];
    int tid = threadIdx.x;
    if (tid < 96) sw[tid] = W0[tid];
    if (tid < 32) sb[tid] = b0[tid];
    __syncthreads();
    int i = blockIdx.x * blockDim.x + tid;
    if (i >= n * 32) return;
    int node = i >> 5, f = i & 31;
    int dg = g_deg[node];
    float di = (dg > 0) ? rsqrtf((float)dg) : 0.f;
    int cnt = g_cnt[node];
    if (cnt > CAP) cnt = CAP;
    int pv = (cnt + 3) & ~3;
    if (pv > CAP) pv = CAP;
    if (f == 0) {
        g_dinv[node] = di;
        g_len[node] = pv;
    }
    if (f < pv - cnt) g_src[node * CAP + cnt + f] = n;   // pad -> zero shadow row
    float x0 = x[node * 3 + 0];
    float x1 = x[node * 3 + 1];
    float x2 = x[node * 3 + 2];
    float o = sb[f] + x0 * sw[f] + x1 * sw[32 + f] + x2 * sw[64 + f];
    o = fmaxf(o, 0.f);
    ((float*)g_h)[i] = o;
    float o_hi = __shfl_down_sync(0xffffffffu, o, 1);
    if ((f & 1) == 0)
        ((__half2*)s_h)[node * 16 + (f >> 1)] = __floats2half2_rn(di * o, di * o_hi);
}

// -------- fp16 quad reduce: sum 4 edge rows in fp16 (HADD2 tree), convert once, fp32 acc --------
__device__ __forceinline__ void quad4(uint2 r0, uint2 r1, uint2 r2, uint2 r3, float4& acc) {
    __half2 a0 = __hadd2(*reinterpret_cast<__half2*>(&r0.x), *reinterpret_cast<__half2*>(&r1.x));
    __half2 a1 = __hadd2(*reinterpret_cast<__half2*>(&r0.y), *reinterpret_cast<__half2*>(&r1.y));
    __half2 b0 = __hadd2(*reinterpret_cast<__half2*>(&r2.x), *reinterpret_cast<__half2*>(&r3.x));
    __half2 b1 = __hadd2(*reinterpret_cast<__half2*>(&r2.y), *reinterpret_cast<__half2*>(&r3.y));
    float2 f0 = __half22float2(__hadd2(a0, b0));
    float2 f1 = __half22float2(__hadd2(a1, b1));
    acc.x += f0.x; acc.y += f0.y; acc.z += f1.x; acc.w += f1.y;
}

// -------- fp16 group gather (bucketed, padded, 8-edge unrolled): 8-lane group per row --------
__device__ __forceinline__ float4 gatherH8(const uint2* __restrict__ rows,
                                           int s, int e, int c) {
    float4 acc = make_float4(0.f, 0.f, 0.f, 0.f);
    int i = s;
    for (; i + 8 <= e; i += 8) {
        int4 ia = __ldg((const int4*)&g_src[i]);
        int4 ib = __ldg((const int4*)&g_src[i + 4]);
        uint2 r0 = __ldg(&rows[ia.x * 8 + c]);
        uint2 r1 = __ldg(&rows[ia.y * 8 + c]);
        uint2 r2 = __ldg(&rows[ia.z * 8 + c]);
        uint2 r3 = __ldg(&rows[ia.w * 8 + c]);
        uint2 r4 = __ldg(&rows[ib.x * 8 + c]);
        uint2 r5 = __ldg(&rows[ib.y * 8 + c]);
        uint2 r6 = __ldg(&rows[ib.z * 8 + c]);
        uint2 r7 = __ldg(&rows[ib.w * 8 + c]);
        quad4(r0, r1, r2, r3, acc);
        quad4(r4, r5, r6, r7, acc);
    }
    if (i < e) {   // exactly 4 remain (rows padded to multiples of 4)
        int4 ia = __ldg((const int4*)&g_src[i]);
        uint2 r0 = __ldg(&rows[ia.x * 8 + c]);
        uint2 r1 = __ldg(&rows[ia.y * 8 + c]);
        uint2 r2 = __ldg(&rows[ia.z * 8 + c]);
        uint2 r3 = __ldg(&rows[ia.w * 8 + c]);
        quad4(r0, r1, r2, r3, acc);
    }
    return acc;
}

__device__ __forceinline__ uint2 pack4(float a, float b, float c, float d) {
    __half2 h0 = __floats2half2_rn(a, b);
    __half2 h1 = __floats2half2_rn(c, d);
    uint2 r;
    r.x = *reinterpret_cast<unsigned*>(&h0);
    r.y = *reinterpret_cast<unsigned*>(&h1);
    return r;
}

// fp16x4 (uint2) -> float4
__device__ __forceinline__ float4 cvt4(uint2 v) {
    float2 f0 = __half22float2(*reinterpret_cast<__half2*>(&v.x));
    float2 f1 = __half22float2(*reinterpret_cast<__half2*>(&v.y));
    return make_float4(f0.x, f0.y, f1.x, f1.y);
}

// ---------------- prop: T1 = L~ x ; warp = 4 rows, 8-lane group per row ----------------
__global__ void k_prop(int in_id, int n) {
    const uint2* __restrict__ xin = hbuf(in_id);
    int t = blockIdx.x * blockDim.x + threadIdx.x;
    int lane = threadIdx.x & 31;
    int row = ((t >> 5) << 2) + (lane >> 3);
    int c = lane & 7;
    if (row >= n) return;
    int s = row * CAP;
    int e = s + g_len[row];
    float4 acc = gatherH8(xin, s, e, c);
    float di = g_dinv[row];
    float4 r = make_float4(-di * acc.x, -di * acc.y, -di * acc.z, -di * acc.w);
    g_t[row * 8 + c] = r;
    s_t[row * 8 + c] = pack4(di * r.x, di * r.y, di * r.z, di * r.w);
}

// ---------------- fused second prop + tiled Chebyshev combine (fp16 sT staging) ----------------
__global__ void __launch_bounds__(256) k_comb(int t0_id, int resid_id, int out_id,
                       const float* __restrict__ Wc, const float* __restrict__ bc, int n,
                       int fuse_final, const float* __restrict__ W1,
                       const float* __restrict__ b1, float* __restrict__ fout) {
    __shared__ __half sTh[32][100];     // fp16 staged [t0|t1|t2], pitch 100 halves
    __shared__ float sWt[32][100];
    __shared__ float sO[32][33];
    const float4* __restrict__ t0f = fbuf(t0_id);
    float4* __restrict__ outf = fbuf(out_id);
    uint2* __restrict__ outs = hbuf(out_id);

    int tid = threadIdx.x;
    int wid = tid >> 5, lane = tid & 31;
    int base = blockIdx.x << 5;

#pragma unroll
    for (int rep = 0; rep < 12; rep++) {
        int idx = rep * 256 + tid;
        sWt[idx & 31][idx >> 5] = Wc[idx];
    }

    // gather phase: warp's 4 groups = 4 nodes
    {
        int grp = lane >> 3, c = lane & 7;
        int nl = (wid << 2) + grp;
        int node = base + nl;
        if (node < n) {
            int s = node * CAP;
            int e = s + g_len[node];
            float4 acc = gatherH8(s_t, s, e, c);
            float di = g_dinv[node];
            float4 t0 = t0f[node * 8 + c];
            float4 t1 = g_t[node * 8 + c];
            float m = -2.f * di;
            float4 t2;
            t2.x = fmaf(m, acc.x, -t0.x);
            t2.y = fmaf(m, acc.y, -t0.y);
            t2.z = fmaf(m, acc.z, -t0.z);
            t2.w = fmaf(m, acc.w, -t0.w);
            *(uint2*)&sTh[nl][c * 4]      = pack4(t0.x, t0.y, t0.z, t0.w);
            *(uint2*)&sTh[nl][32 + c * 4] = pack4(t1.x, t1.y, t1.z, t1.w);
            *(uint2*)&sTh[nl][64 + c * 4] = pack4(t2.x, t2.y, t2.z, t2.w);
        }
    }
    __syncthreads();

    // dense phase: warp wid -> features {wid, wid+8, wid+16, wid+24}, node = lane
    {
        float acc0 = __ldg(&bc[wid]);
        float acc1 = __ldg(&bc[wid + 8]);
        float acc2 = __ldg(&bc[wid + 16]);
        float acc3 = __ldg(&bc[wid + 24]);
#pragma unroll
        for (int kc = 0; kc < 24; kc++) {
            float4 t = cvt4(*(const uint2*)&sTh[lane][kc * 4]);
            float4 w0 = *(const float4*)&sWt[wid][kc * 4];
            float4 w1 = *(const float4*)&sWt[wid + 8][kc * 4];
            float4 w2 = *(const float4*)&sWt[wid + 16][kc * 4];
            float4 w3 = *(const float4*)&sWt[wid + 24][kc * 4];
            acc0 += t.x * w0.x + t.y * w0.y + t.z * w0.z + t.w * w0.w;
            acc1 += t.x * w1.x + t.y * w1.y + t.z * w1.z + t.w * w1.w;
            acc2 += t.x * w2.x + t.y * w2.y + t.z * w2.z + t.w * w2.w;
            acc3 += t.x * w3.x + t.y * w3.y + t.z * w3.z + t.w * w3.w;
        }
        sO[lane][wid]      = acc0;
        sO[lane][wid + 8]  = acc1;
        sO[lane][wid + 16] = acc2;
        sO[lane][wid + 24] = acc3;
    }
    __syncthreads();

    // epilogue: resid + relu + stores (+ fused output layer, + counter reset on last conv)
    {
        int nl = tid >> 3, cc = tid & 7;
        int node = base + nl;
        if (node < n) {
            float4 o;
            o.x = sO[nl][cc * 4 + 0];
            o.y = sO[nl][cc * 4 + 1];
            o.z = sO[nl][cc * 4 + 2];
            o.w = sO[nl][cc * 4 + 3];
            if (resid_id >= 0) {
                float4 rv = fbuf(resid_id)[node * 8 + cc];
                o.x += rv.x; o.y += rv.y; o.z += rv.z; o.w += rv.w;
            }
            o.x = fmaxf(o.x, 0.f); o.y = fmaxf(o.y, 0.f);
            o.z = fmaxf(o.z, 0.f); o.w = fmaxf(o.w, 0.f);
            outf[node * 8 + cc] = o;
            float di = g_dinv[node];
            outs[node * 8 + cc] = pack4(di * o.x, di * o.y, di * o.z, di * o.w);
            if (fuse_final) {
                float4 wv = __ldg(&((const float4*)W1)[cc]);
                float part = o.x * wv.x + o.y * wv.y + o.z * wv.z + o.w * wv.w;
#pragma unroll
                for (int m = 1; m <= 4; m <<= 1)
                    part += __shfl_xor_sync(0xffffffffu, part, m);
                if (cc == 0) {
                    fout[node] = part + b1[0];
                    g_cnt[node] = 0;     // reset for next graph replay
                    g_deg[node] = 0;
                }
            }
        }
    }
}

// ---------------- launch ----------------
extern "C" void kernel_launch(void* const* d_in, const int* in_sizes, int n_in,
                              void* d_out, int out_size) {
    const float* x    = (const float*)d_in[0];
    const void*  ei   = d_in[1];
    const float* W0   = (const float*)d_in[2];
    const float* b0   = (const float*)d_in[3];
    const float* c11W = (const float*)d_in[4];
    const float* c11b = (const float*)d_in[5];
    const float* c12W = (const float*)d_in[6];
    const float* c12b = (const float*)d_in[7];
    const float* c21W = (const float*)d_in[8];
    const float* c21b = (const float*)d_in[9];
    const float* c22W = (const float*)d_in[10];
    const float* c22b = (const float*)d_in[11];
    const float* W1   = (const float*)d_in[12];
    const float* b1   = (const float*)d_in[13];
    float* out = (float*)d_out;

    int n = in_sizes[0] / 3;
    int e = in_sizes[1] / 2;
    if (n > NN) n = NN;
    if (e > EE) e = EE;

    const int B = 256;
    int gE  = (e + B - 1) / B;
    int gNF = (n * 32 + B - 1) / B;   // 32 thr/node (mlp)
    int gP  = (n * 8 + B - 1) / B;    // 8 thr/row (prop)
    int gT  = (n + 31) / 32;          // 32-node tiles (comb)

    // setup: 2 launches -> first k_comb is launch #4 (ncu capture target)
    k_scat<<<gE, B>>>(ei, e);
    k_mlp<<<gNF, B>>>(x, W0, b0, n);

    // ids: 0=h, 1=a, 2=t, 3=b
    // conv11: h -> a
    k_prop<<<gP, B>>>(0, n);
    k_comb<<<gT, B>>>(0, -1, 1, c11W, c11b, n, 0, W1, b1, out);
    // conv12: a -> b, resid h
    k_prop<<<gP, B>>>(1, n);
    k_comb<<<gT, B>>>(1, 0, 3, c12W, c12b, n, 0, W1, b1, out);
    // conv21: b -> a
    k_prop<<<gP, B>>>(3, n);
    k_comb<<<gT, B>>>(3, -1, 1, c21W, c21b, n, 0, W1, b1, out);
    // conv22: a -> h, resid b (+ fused output layer + counter reset)
    k_prop<<<gP, B>>>(1, n);
    k_comb<<<gT, B>>>(1, 3, 0, c22W, c22b, n, 1, W1, b1, out);
}

// round 17
// speedup vs baseline: 1.1572x; 1.0587x over previous
#include <cuda_runtime.h>
#include <cuda_fp16.h>

#define NN 200000
#define EE 3200000
#define CAP 64                    // per-node bucket capacity (P(overflow) ~ 1e-10)

// ---------------- static device scratch ----------------
__device__ int      g_deg[NN];          // out-degree by src (statically zero; reset by last comb)
__device__ int      g_cnt[NN];          // in-degree by dst / scatter cursor
__device__ float    g_dinv[NN];
__device__ int      g_len[NN];          // padded row length
__device__ int      g_src[NN * CAP];    // bucketed CSR
__device__ float4   g_h[NN * 8];        // raw fp32 features
__device__ float4   g_a[NN * 8];
__device__ float4   g_t[NN * 8];
__device__ float4   g_b[NN * 8];
__device__ uint2    s_h[(NN + 1) * 8];  // fp16 prescaled shadows; row NN stays zero (pad)
__device__ uint2    s_a[(NN + 1) * 8];
__device__ uint2    s_t[(NN + 1) * 8];
__device__ uint2    s_b[(NN + 1) * 8];

__device__ __forceinline__ float4* fbuf(int id) {
    switch (id) { case 0: return g_h; case 1: return g_a; case 2: return g_t; default: return g_b; }
}
__device__ __forceinline__ uint2* hbuf(int id) {
    switch (id) { case 0: return s_h; case 1: return s_a; case 2: return s_t; default: return s_b; }
}

// per-block dtype detection: 1 if edge buffer is int64
__device__ __forceinline__ int detect64(const void* ei) {
    const int* w = (const int*)ei;
    int bad = 0;
#pragma unroll
    for (int k = 0; k < 2; k++) {
        int idx = (threadIdx.x & 31) + 32 * k;
        if (w[2 * idx + 1] != 0) bad = 1;
    }
    return __all_sync(0xffffffffu, bad == 0) ? 1 : 0;
}

__device__ __forceinline__ int edge_at(const void* ei, int idx, int is64) {
    if (is64) return (int)((const long long*)ei)[idx];
    return ((const int*)ei)[idx];
}

// ---------------- single-pass scatter (counts + bucket CSR) ----------------
__global__ void k_scat(const void* ei, int e) {
    int is64 = detect64(ei);
    int i = blockIdx.x * blockDim.x + threadIdx.x;
    if (i < e) {
        int s = edge_at(ei, i, is64);
        int d = edge_at(ei, e + i, is64);
        atomicAdd(&g_deg[s], 1);
        int p = atomicAdd(&g_cnt[d], 1);
        if (p < CAP) g_src[d * CAP + p] = s;
    }
}

// ---------------- dinv + row pad + input MLP + fp16 shadow (32 thr/node) ----------------
__global__ void k_mlp(const float* __restrict__ x, const float* __restrict__ W0,
                      const float* __restrict__ b0, int n) {
    __shared__ float sw[96];
    __shared__ float sb[32];
    int tid = threadIdx.x;
    if (tid < 96) sw[tid] = W0[tid];
    if (tid < 32) sb[tid] = b0[tid];
    __syncthreads();
    int i = blockIdx.x * blockDim.x + tid;
    if (i >= n * 32) return;
    int node = i >> 5, f = i & 31;
    int dg = g_deg[node];
    float di = (dg > 0) ? rsqrtf((float)dg) : 0.f;
    int cnt = g_cnt[node];
    if (cnt > CAP) cnt = CAP;
    int pv = (cnt + 3) & ~3;
    if (pv > CAP) pv = CAP;
    if (f == 0) {
        g_dinv[node] = di;
        g_len[node] = pv;
    }
    if (f < pv - cnt) g_src[node * CAP + cnt + f] = n;   // pad -> zero shadow row
    float x0 = x[node * 3 + 0];
    float x1 = x[node * 3 + 1];
    float x2 = x[node * 3 + 2];
    float o = sb[f] + x0 * sw[f] + x1 * sw[32 + f] + x2 * sw[64 + f];
    o = fmaxf(o, 0.f);
    ((float*)g_h)[i] = o;
    float o_hi = __shfl_down_sync(0xffffffffu, o, 1);
    if ((f & 1) == 0)
        ((__half2*)s_h)[node * 16 + (f >> 1)] = __floats2half2_rn(di * o, di * o_hi);
}

// -------- fp16 quad reduce: sum 4 edge rows in fp16 (HADD2 tree), convert once, fp32 acc --------
__device__ __forceinline__ void quad4(uint2 r0, uint2 r1, uint2 r2, uint2 r3, float4& acc) {
    __half2 a0 = __hadd2(*reinterpret_cast<__half2*>(&r0.x), *reinterpret_cast<__half2*>(&r1.x));
    __half2 a1 = __hadd2(*reinterpret_cast<__half2*>(&r0.y), *reinterpret_cast<__half2*>(&r1.y));
    __half2 b0 = __hadd2(*reinterpret_cast<__half2*>(&r2.x), *reinterpret_cast<__half2*>(&r3.x));
    __half2 b1 = __hadd2(*reinterpret_cast<__half2*>(&r2.y), *reinterpret_cast<__half2*>(&r3.y));
    float2 f0 = __half22float2(__hadd2(a0, b0));
    float2 f1 = __half22float2(__hadd2(a1, b1));
    acc.x += f0.x; acc.y += f0.y; acc.z += f1.x; acc.w += f1.y;
}

// -------- fp16 group gather (bucketed, padded, 8-edge unrolled): 8-lane group per row --------
__device__ __forceinline__ float4 gatherH8(const uint2* __restrict__ rows,
                                           int s, int e, int c) {
    float4 acc = make_float4(0.f, 0.f, 0.f, 0.f);
    int i = s;
    for (; i + 8 <= e; i += 8) {
        int4 ia = __ldg((const int4*)&g_src[i]);
        int4 ib = __ldg((const int4*)&g_src[i + 4]);
        uint2 r0 = __ldg(&rows[ia.x * 8 + c]);
        uint2 r1 = __ldg(&rows[ia.y * 8 + c]);
        uint2 r2 = __ldg(&rows[ia.z * 8 + c]);
        uint2 r3 = __ldg(&rows[ia.w * 8 + c]);
        uint2 r4 = __ldg(&rows[ib.x * 8 + c]);
        uint2 r5 = __ldg(&rows[ib.y * 8 + c]);
        uint2 r6 = __ldg(&rows[ib.z * 8 + c]);
        uint2 r7 = __ldg(&rows[ib.w * 8 + c]);
        quad4(r0, r1, r2, r3, acc);
        quad4(r4, r5, r6, r7, acc);
    }
    if (i < e) {   // exactly 4 remain (rows padded to multiples of 4)
        int4 ia = __ldg((const int4*)&g_src[i]);
        uint2 r0 = __ldg(&rows[ia.x * 8 + c]);
        uint2 r1 = __ldg(&rows[ia.y * 8 + c]);
        uint2 r2 = __ldg(&rows[ia.z * 8 + c]);
        uint2 r3 = __ldg(&rows[ia.w * 8 + c]);
        quad4(r0, r1, r2, r3, acc);
    }
    return acc;
}

__device__ __forceinline__ uint2 pack4(float a, float b, float c, float d) {
    __half2 h0 = __floats2half2_rn(a, b);
    __half2 h1 = __floats2half2_rn(c, d);
    uint2 r;
    r.x = *reinterpret_cast<unsigned*>(&h0);
    r.y = *reinterpret_cast<unsigned*>(&h1);
    return r;
}

// fp16x4 (uint2) -> float4
__device__ __forceinline__ float4 cvt4(uint2 v) {
    float2 f0 = __half22float2(*reinterpret_cast<__half2*>(&v.x));
    float2 f1 = __half22float2(*reinterpret_cast<__half2*>(&v.y));
    return make_float4(f0.x, f0.y, f1.x, f1.y);
}

// ---------------- prop: T1 = L~ x ; warp = 4 rows, 8-lane group per row ----------------
__global__ void k_prop(int in_id, int n) {
    const uint2* __restrict__ xin = hbuf(in_id);
    int t = blockIdx.x * blockDim.x + threadIdx.x;
    int lane = threadIdx.x & 31;
    int row = ((t >> 5) << 2) + (lane >> 3);
    int c = lane & 7;
    if (row >= n) return;
    int s = row * CAP;
    int e = s + g_len[row];
    float4 acc = gatherH8(xin, s, e, c);
    float di = g_dinv[row];
    float4 r = make_float4(-di * acc.x, -di * acc.y, -di * acc.z, -di * acc.w);
    g_t[row * 8 + c] = r;
    s_t[row * 8 + c] = pack4(di * r.x, di * r.y, di * r.z, di * r.w);
}

// ---------------- fused second prop + 64-node tiled Chebyshev combine ----------------
// two 32-node sub-tiles per block; dense phase loads each weight quad once, applies to both
__global__ void __launch_bounds__(256) k_comb(int t0_id, int resid_id, int out_id,
                       const float* __restrict__ Wc, const float* __restrict__ bc, int n,
                       int fuse_final, const float* __restrict__ W1,
                       const float* __restrict__ b1, float* __restrict__ fout) {
    __shared__ __half sTh[64][100];     // fp16 staged [t0|t1|t2] for 64 nodes
    __shared__ float sWt[32][100];
    __shared__ float sO[64][33];
    const float4* __restrict__ t0f = fbuf(t0_id);
    float4* __restrict__ outf = fbuf(out_id);
    uint2* __restrict__ outs = hbuf(out_id);

    int tid = threadIdx.x;
    int wid = tid >> 5, lane = tid & 31;
    int base = blockIdx.x << 6;

#pragma unroll
    for (int rep = 0; rep < 12; rep++) {
        int idx = rep * 256 + tid;
        sWt[idx & 31][idx >> 5] = Wc[idx];
    }

    // gather phase: warp gathers 8 nodes (4 per sub-tile)
    {
        int grp = lane >> 3, c = lane & 7;
#pragma unroll
        for (int rep = 0; rep < 2; rep++) {
            int nl = rep * 32 + (wid << 2) + grp;
            int node = base + nl;
            if (node < n) {
                int s = node * CAP;
                int e = s + g_len[node];
                float4 acc = gatherH8(s_t, s, e, c);
                float di = g_dinv[node];
                float4 t0 = t0f[node * 8 + c];
                float4 t1 = g_t[node * 8 + c];
                float m = -2.f * di;
                float4 t2;
                t2.x = fmaf(m, acc.x, -t0.x);
                t2.y = fmaf(m, acc.y, -t0.y);
                t2.z = fmaf(m, acc.z, -t0.z);
                t2.w = fmaf(m, acc.w, -t0.w);
                *(uint2*)&sTh[nl][c * 4]      = pack4(t0.x, t0.y, t0.z, t0.w);
                *(uint2*)&sTh[nl][32 + c * 4] = pack4(t1.x, t1.y, t1.z, t1.w);
                *(uint2*)&sTh[nl][64 + c * 4] = pack4(t2.x, t2.y, t2.z, t2.w);
            }
        }
    }
    __syncthreads();

    // dense phase: warp wid -> features {wid, wid+8, wid+16, wid+24};
    // sub-tile A node = lane, sub-tile B node = 32 + lane; weights loaded once per kc
    {
        float a0 = __ldg(&bc[wid]);
        float a1 = __ldg(&bc[wid + 8]);
        float a2 = __ldg(&bc[wid + 16]);
        float a3 = __ldg(&bc[wid + 24]);
        float b0v = a0, b1v = a1, b2v = a2, b3v = a3;
#pragma unroll
        for (int kc = 0; kc < 24; kc++) {
            float4 w0 = *(const float4*)&sWt[wid][kc * 4];
            float4 w1 = *(const float4*)&sWt[wid + 8][kc * 4];
            float4 w2 = *(const float4*)&sWt[wid + 16][kc * 4];
            float4 w3 = *(const float4*)&sWt[wid + 24][kc * 4];
            float4 ta = cvt4(*(const uint2*)&sTh[lane][kc * 4]);
            float4 tb = cvt4(*(const uint2*)&sTh[32 + lane][kc * 4]);
            a0 += ta.x * w0.x + ta.y * w0.y + ta.z * w0.z + ta.w * w0.w;
            a1 += ta.x * w1.x + ta.y * w1.y + ta.z * w1.z + ta.w * w1.w;
            a2 += ta.x * w2.x + ta.y * w2.y + ta.z * w2.z + ta.w * w2.w;
            a3 += ta.x * w3.x + ta.y * w3.y + ta.z * w3.z + ta.w * w3.w;
            b0v += tb.x * w0.x + tb.y * w0.y + tb.z * w0.z + tb.w * w0.w;
            b1v += tb.x * w1.x + tb.y * w1.y + tb.z * w1.z + tb.w * w1.w;
            b2v += tb.x * w2.x + tb.y * w2.y + tb.z * w2.z + tb.w * w2.w;
            b3v += tb.x * w3.x + tb.y * w3.y + tb.z * w3.z + tb.w * w3.w;
        }
        sO[lane][wid]      = a0;
        sO[lane][wid + 8]  = a1;
        sO[lane][wid + 16] = a2;
        sO[lane][wid + 24] = a3;
        sO[32 + lane][wid]      = b0v;
        sO[32 + lane][wid + 8]  = b1v;
        sO[32 + lane][wid + 16] = b2v;
        sO[32 + lane][wid + 24] = b3v;
    }
    __syncthreads();

    // epilogue: both sub-tiles; resid + relu + stores (+ fused final, + counter reset)
    {
        int nl = tid >> 3, cc = tid & 7;
#pragma unroll
        for (int rep = 0; rep < 2; rep++) {
            int nn = rep * 32 + nl;
            int node = base + nn;
            if (node < n) {
                float4 o;
                o.x = sO[nn][cc * 4 + 0];
                o.y = sO[nn][cc * 4 + 1];
                o.z = sO[nn][cc * 4 + 2];
                o.w = sO[nn][cc * 4 + 3];
                if (resid_id >= 0) {
                    float4 rv = fbuf(resid_id)[node * 8 + cc];
                    o.x += rv.x; o.y += rv.y; o.z += rv.z; o.w += rv.w;
                }
                o.x = fmaxf(o.x, 0.f); o.y = fmaxf(o.y, 0.f);
                o.z = fmaxf(o.z, 0.f); o.w = fmaxf(o.w, 0.f);
                outf[node * 8 + cc] = o;
                float di = g_dinv[node];
                outs[node * 8 + cc] = pack4(di * o.x, di * o.y, di * o.z, di * o.w);
                if (fuse_final) {
                    float4 wv = __ldg(&((const float4*)W1)[cc]);
                    float part = o.x * wv.x + o.y * wv.y + o.z * wv.z + o.w * wv.w;
#pragma unroll
                    for (int m = 1; m <= 4; m <<= 1)
                        part += __shfl_xor_sync(0xffffffffu, part, m);
                    if (cc == 0) {
                        fout[node] = part + b1[0];
                        g_cnt[node] = 0;     // reset for next graph replay
                        g_deg[node] = 0;
                    }
                }
            }
        }
    }
}

// ---------------- launch ----------------
extern "C" void kernel_launch(void* const* d_in, const int* in_sizes, int n_in,
                              void* d_out, int out_size) {
    const float* x    = (const float*)d_in[0];
    const void*  ei   = d_in[1];
    const float* W0   = (const float*)d_in[2];
    const float* b0   = (const float*)d_in[3];
    const float* c11W = (const float*)d_in[4];
    const float* c11b = (const float*)d_in[5];
    const float* c12W = (const float*)d_in[6];
    const float* c12b = (const float*)d_in[7];
    const float* c21W = (const float*)d_in[8];
    const float* c21b = (const float*)d_in[9];
    const float* c22W = (const float*)d_in[10];
    const float* c22b = (const float*)d_in[11];
    const float* W1   = (const float*)d_in[12];
    const float* b1   = (const float*)d_in[13];
    float* out = (float*)d_out;

    int n = in_sizes[0] / 3;
    int e = in_sizes[1] / 2;
    if (n > NN) n = NN;
    if (e > EE) e = EE;

    const int B = 256;
    int gE  = (e + B - 1) / B;
    int gNF = (n * 32 + B - 1) / B;   // 32 thr/node (mlp)
    int gP  = (n * 8 + B - 1) / B;    // 8 thr/row (prop)
    int gT  = (n + 63) / 64;          // 64-node tiles (comb)

    // setup: 2 launches -> first k_comb is launch #4 (ncu capture target)
    k_scat<<<gE, B>>>(ei, e);
    k_mlp<<<gNF, B>>>(x, W0, b0, n);

    // ids: 0=h, 1=a, 2=t, 3=b
    // conv11: h -> a
    k_prop<<<gP, B>>>(0, n);
    k_comb<<<gT, B>>>(0, -1, 1, c11W, c11b, n, 0, W1, b1, out);
    // conv12: a -> b, resid h
    k_prop<<<gP, B>>>(1, n);
    k_comb<<<gT, B>>>(1, 0, 3, c12W, c12b, n, 0, W1, b1, out);
    // conv21: b -> a
    k_prop<<<gP, B>>>(3, n);
    k_comb<<<gT, B>>>(3, -1, 1, c21W, c21b, n, 0, W1, b1, out);
    // conv22: a -> h, resid b (+ fused output layer + counter reset)
    k_prop<<<gP, B>>>(1, n);
    k_comb<<<gT, B>>>(1, 3, 0, c22W, c22b, n, 1, W1, b1, out);
}